// round 11
// baseline (speedup 1.0000x reference)
#include <cuda_runtime.h>
#include <cuda_bf16.h>
#include <cstdint>

// Problem constants
#define B_DIM 4
#define S_DIM 256
#define V_DIM 50257u
#define D_DIM 768
#define ROWS (B_DIM * S_DIM)     // 1024
#define D4 (D_DIM / 4)           // 192 float4 per output row
#define HALF_D4 (D4 / 2)         // 96 float4 per half-gather
#define SPLIT 25128u             // front half [0,SPLIT), back half [SPLIT,V)
#define NTH 256
#define BATCH 4                  // float4 loads per thread per chunk (16KB chunk)

// Per-row hit record: 0 = unset. low32 = col+1, high32 = float bits of val.
// A single aligned 8-byte store publishes both flag and payload atomically.
// Self-cleaning: the non-finder half resets its row to 0 after consuming it,
// so every launch (and every graph replay) starts from the all-zero state.
__device__ unsigned long long g_hit[ROWS];

__device__ __forceinline__ bool nz4(float4 v)
{
    return ((__float_as_uint(v.x) | __float_as_uint(v.y) |
             __float_as_uint(v.z) | __float_as_uint(v.w)) != 0u);
}

__global__ void __launch_bounds__(NTH)
half_row_scan_kernel(const float*  __restrict__ oh,
                     const float4* __restrict__ weight,
                     float4*       __restrict__ out)
{
    __shared__ int   s_col;
    __shared__ float s_val;
    __shared__ int   s_found;

    const unsigned int row  = blockIdx.x >> 1;
    const unsigned int half = blockIdx.x & 1u;
    const unsigned int tid  = threadIdx.x;

    if (tid == 0) s_found = 0;
    __syncthreads();

    // This block's flat element range [lo, hi).
    const unsigned int a  = row * V_DIM;
    const unsigned int lo = a + (half ? SPLIT : 0u);
    const unsigned int hi = a + (half ? V_DIM : SPLIT);

    const unsigned int first4  = (lo + 3u) & ~3u;
    const unsigned int body4s  = first4 >> 2;   // float4 idx, inclusive
    const unsigned int body4e  = hi >> 2;       // float4 idx, exclusive

    volatile unsigned int* gpoll =
        (volatile unsigned int*)&g_hit[row];    // low word (little-endian)

    // Records a found nonzero into shared + global.
    auto record = [&](float val, unsigned int flat) {
        unsigned int col = flat - a;
        s_col = (int)col;
        s_val = val;
        g_hit[row] = ((unsigned long long)__float_as_uint(val) << 32)
                   | (unsigned long long)(col + 1u);
        __threadfence();          // hurry global visibility (rare path)
        __threadfence_block();
        s_found = 1;
    };

    // --- scalar head (<=3 elems) ---
    if (tid < 4u && lo + tid < first4) {
        float v = oh[lo + tid];
        if (v != 0.0f) record(v, lo + tid);
    }
    // --- scalar tail (<=3 elems) ---
    if (tid < 4u) {
        unsigned int e = (body4e << 2) + tid;
        if (e < hi) {
            float v = oh[e];
            if (v != 0.0f) record(v, e);
        }
    }

    // --- float4 body: uniform 16KB chunks, poll both flags per chunk ---
    const float4* __restrict__ oh4 = (const float4*)oh;
    volatile int* vfound = &s_found;

    unsigned int base = body4s;
    for (; base + BATCH * NTH <= body4e; base += BATCH * NTH) {
        int f = *vfound | (int)(*gpoll != 0u);   // LDS + L2 load, hide under LDGs
        float4 v[BATCH];
        #pragma unroll
        for (int k = 0; k < BATCH; ++k)
            v[k] = __ldcs(&oh4[base + (unsigned int)k * NTH + tid]);
        if (f) { base += BATCH * NTH; goto scan_done; }

        #pragma unroll
        for (int k = 0; k < BATCH; ++k) {
            if (nz4(v[k])) {
                unsigned int fb = (base + (unsigned int)k * NTH + tid) * 4u;
                float vals[4] = {v[k].x, v[k].y, v[k].z, v[k].w};
                #pragma unroll
                for (int l = 0; l < 4; ++l)
                    if (vals[l] != 0.0f) record(vals[l], fb + (unsigned int)l);
            }
        }
    }
    // remainder (< one chunk)
    if (!*vfound && *gpoll == 0u) {
        for (unsigned int j = base + tid; j < body4e; j += NTH) {
            float4 v = __ldcs(&oh4[j]);
            if (nz4(v)) {
                unsigned int fb = j * 4u;
                float vals[4] = {v.x, v.y, v.z, v.w};
                #pragma unroll
                for (int l = 0; l < 4; ++l)
                    if (vals[l] != 0.0f) record(vals[l], fb + (unsigned int)l);
            }
        }
    }
scan_done:
    __syncthreads();   // s_found / s_col / s_val coherent across block

    int   col;
    float sval;
    if (s_found) {
        // This block found the hit itself (finder half). Does NOT touch g_hit.
        col  = s_col;
        sval = s_val;
    } else {
        // Non-finder half: wait for sibling's record (usually already set).
        unsigned long long h;
        volatile unsigned long long* gh = (volatile unsigned long long*)&g_hit[row];
        while ((h = *gh) == 0ull) { __nanosleep(64); }
        col  = (int)(unsigned int)(h & 0xffffffffu) - 1;
        sval = __uint_as_float((unsigned int)(h >> 32));
        __syncthreads();                 // all threads have consumed h
        if (tid == 0) g_hit[row] = 0ull; // self-clean for the next launch
    }

    // --- split gather: this half writes its 96 float4s of the output row ---
    if (tid < HALF_D4) {
        unsigned int d = half * HALF_D4 + tid;
        float4 w = __ldg(&weight[(size_t)col * D4 + d]);
        float4 o;
        o.x = sval * w.x;
        o.y = sval * w.y;
        o.z = sval * w.z;
        o.w = sval * w.w;
        out[(size_t)row * D4 + d] = o;
    }
}

// ---------------------------------------------------------------------------
// Launch: d_in[0] = one_hot [B,S,V] f32, d_in[1] = weight [V,D] f32.
// Output [B,S,D] f32. Single kernel, two blocks per row (front/back half).
// ---------------------------------------------------------------------------
extern "C" void kernel_launch(void* const* d_in, const int* in_sizes, int n_in,
                              void* d_out, int out_size)
{
    const float*  oh     = (const float*)d_in[0];
    const float4* weight = (const float4*)d_in[1];
    float4*       out    = (float4*)d_out;

    (void)in_sizes; (void)n_in; (void)out_size;

    half_row_scan_kernel<<<ROWS * 2, NTH>>>(oh, weight, out);
}

// round 12
// speedup vs baseline: 1.2128x; 1.2128x over previous
#include <cuda_runtime.h>
#include <cuda_bf16.h>
#include <cstdint>

// Problem constants
#define B_DIM 4
#define S_DIM 256
#define V_DIM 50257u
#define D_DIM 768
#define ROWS (B_DIM * S_DIM)     // 1024
#define D4 (D_DIM / 4)           // 192 float4 per output row
#define NTH 512
#define BATCH 2                  // float4 per thread per chunk -> 16KB chunks
#define CH (BATCH * NTH)         // 1024 float4 per chunk

// ---------------------------------------------------------------------------
// One block per row (fully independent -> safe oversubscription/backfill),
// 512 threads, software-pipelined 16KB chunks with shared-flag early exit.
//   - prefetch chunk c+1 before processing chunk c: no load->test stall
//   - flag is LDS-only (29cyc), read at chunk top, hidden under LDGs
//   - grid 1024 > residency (~444): early-exit rows free slots for later
//     rows => drain phase replaced by backfill, tail ~ one solo row
// Row stride 50257 % 4 == 1: scalar head/tail (<=3 each) + float4 body.
// OOB lanes in the last chunk load zeros (never record).
// ---------------------------------------------------------------------------
__device__ __forceinline__ bool nz4(float4 v)
{
    return ((__float_as_uint(v.x) | __float_as_uint(v.y) |
             __float_as_uint(v.z) | __float_as_uint(v.w)) != 0u);
}

__global__ void __launch_bounds__(NTH)
row_scan_pipe_kernel(const float*  __restrict__ oh,
                     const float4* __restrict__ weight,
                     float4*       __restrict__ out)
{
    __shared__ int   s_col;
    __shared__ float s_val;
    __shared__ int   s_found;

    const unsigned int row = blockIdx.x;
    const unsigned int tid = threadIdx.x;

    if (tid == 0) s_found = 0;
    __syncthreads();

    // Flat element range of this row: [a, end). 51.5M total fits in 32 bits.
    const unsigned int a       = row * V_DIM;
    const unsigned int end     = a + V_DIM;
    const unsigned int first4  = (a + 3u) & ~3u;
    const unsigned int body4s  = first4 >> 2;       // float4 idx, inclusive
    const unsigned int body4e  = end >> 2;          // float4 idx, exclusive

    // --- scalar head (<=3 elems) ---
    if (tid < 4u && a + tid < first4) {
        float v = oh[a + tid];
        if (v != 0.0f) {
            s_col = (int)tid; s_val = v;
            __threadfence_block();
            s_found = 1;
        }
    }
    // --- scalar tail (<=3 elems) ---
    if (tid < 4u) {
        unsigned int e = (body4e << 2) + tid;
        if (e < end) {
            float v = oh[e];
            if (v != 0.0f) {
                s_col = (int)(e - a); s_val = v;
                __threadfence_block();
                s_found = 1;
            }
        }
    }

    // --- pipelined float4 body ---
    const float4* __restrict__ oh4 = (const float4*)oh;
    volatile int* vfound = &s_found;
    const float4 z4 = make_float4(0.f, 0.f, 0.f, 0.f);

    const unsigned int nchunks = (body4e - body4s + CH - 1u) / CH;
    unsigned int i = body4s + tid;

    // prologue: load chunk 0 (bounded)
    float4 cur[BATCH];
    #pragma unroll
    for (int k = 0; k < BATCH; ++k) {
        unsigned int j = i + (unsigned int)k * NTH;
        cur[k] = (j < body4e) ? __ldcs(&oh4[j]) : z4;
    }

    for (unsigned int c = 0; c < nchunks; ++c) {
        int f = *vfound;                       // LDS: resolves under the LDGs

        // prefetch next chunk (bounded); zeros if past the end
        float4 nxt[BATCH];
        unsigned int ni = i + CH;
        #pragma unroll
        for (int k = 0; k < BATCH; ++k) {
            unsigned int j = ni + (unsigned int)k * NTH;
            nxt[k] = (c + 1u < nchunks && j < body4e) ? __ldcs(&oh4[j]) : z4;
        }

        if (f) break;                          // hit found: our data is zeros

        // process current chunk (data requested a full iteration ago: ready)
        #pragma unroll
        for (int k = 0; k < BATCH; ++k) {
            if (nz4(cur[k])) {
                unsigned int fb = (i + (unsigned int)k * NTH) * 4u;
                float vals[4] = {cur[k].x, cur[k].y, cur[k].z, cur[k].w};
                #pragma unroll
                for (int l = 0; l < 4; ++l)
                    if (vals[l] != 0.0f) {
                        s_col = (int)(fb + (unsigned int)l - a);
                        s_val = vals[l];
                        __threadfence_block();
                        s_found = 1;
                    }
            }
        }

        #pragma unroll
        for (int k = 0; k < BATCH; ++k) cur[k] = nxt[k];
        i = ni;
    }

    __syncthreads();   // s_col / s_val now safely visible

    // --- gather: out[row][:] = s_val * weight[s_col][:] ---
    const int   col = s_col;
    const float s   = s_val;
    if (tid < D4) {
        float4 w = __ldg(&weight[(size_t)col * D4 + tid]);
        float4 o;
        o.x = s * w.x;
        o.y = s * w.y;
        o.z = s * w.z;
        o.w = s * w.w;
        out[(size_t)row * D4 + tid] = o;
    }
}

// ---------------------------------------------------------------------------
// Launch: d_in[0] = one_hot [B,S,V] f32, d_in[1] = weight [V,D] f32.
// Output [B,S,D] f32. Single kernel, one independent block per row.
// ---------------------------------------------------------------------------
extern "C" void kernel_launch(void* const* d_in, const int* in_sizes, int n_in,
                              void* d_out, int out_size)
{
    const float*  oh     = (const float*)d_in[0];
    const float4* weight = (const float4*)d_in[1];
    float4*       out    = (float4*)d_out;

    (void)in_sizes; (void)n_in; (void)out_size;

    row_scan_pipe_kernel<<<ROWS, NTH>>>(oh, weight, out);
}